// round 13
// baseline (speedup 1.0000x reference)
#include <cuda_runtime.h>
#include <math.h>

#define FULLM 0xffffffffu
#define MINN 1e-15f
#define MAXNORM 0.996f        // (1 - 0.004) / sqrt(c), c = 1
#define ATANH_MAX 3.1063030f  // artanh(0.996)

typedef unsigned long long ull;

// ---------------- device scratch ----------------
__device__ float g_p[24576 * 32];   // ball-mapped rows (3.1MB, L2-resident)
__device__ float g_lam[24576];      // artanh(|p|)/|p| per row

// ---------------- helpers ----------------
__device__ __forceinline__ float wredsum(float v) {
#pragma unroll
    for (int o = 16; o; o >>= 1) v += __shfl_xor_sync(FULLM, v, o);
    return v;
}
__device__ __forceinline__ void wredsum2(float& a, float& b) {
#pragma unroll
    for (int o = 16; o; o >>= 1) {
        a += __shfl_xor_sync(FULLM, a, o);
        b += __shfl_xor_sync(FULLM, b, o);
    }
}
__device__ __forceinline__ float tanh_fast(float x) {   // x >= 0, clip 15
    x = fminf(x, 15.f);
    float e = __expf(-2.f * x);
    return __fdividef(1.f - e, 1.f + e);
}
__device__ __forceinline__ float artanh_fast(float x) {
    x = fminf(fmaxf(x, -1.f + 1e-7f), 1.f - 1e-7f);
    return 0.5f * __logf(__fdividef(1.f + x, 1.f - x));
}
__device__ __forceinline__ void norm_inv(float s, float& n, float& inv) {
    s = fmaxf(s, 1e-30f);
    inv = __frsqrt_rn(s);
    n = s * inv;
}
// packed f32x2 fma (Blackwell)
__device__ __forceinline__ ull fma2(ull a, ull b, ull c) {
    ull d;
    asm("fma.rn.f32x2 %0, %1, %2, %3;" : "=l"(d) : "l"(a), "l"(b), "l"(c));
    return d;
}
__device__ __forceinline__ void unpack2(ull v, float& lo, float& hi) {
    unsigned l, h;
    asm("mov.b64 {%0, %1}, %2;" : "=r"(l), "=r"(h) : "l"(v));
    lo = __uint_as_float(l);
    hi = __uint_as_float(h);
}

// hyp bias proj(expmap0(b)); warp-collective, writes smem
template <int J>
__device__ __forceinline__ void make_hyp_bias(const float* b, float* hb, float* hbn2) {
    const int lane = threadIdx.x & 31;
    float v[J];
    float s = 0.f;
#pragma unroll
    for (int j = 0; j < J; j++) { v[j] = b[lane * J + j]; s += v[j] * v[j]; }
    float n, inv;
    norm_inv(wredsum(s), n, inv);
    float t = tanh_fast(n);
#pragma unroll
    for (int j = 0; j < J; j++) v[j] *= t * inv;
    float f = (t > MAXNORM) ? __fdividef(MAXNORM, t) : 1.f;
    float vn = fminf(t, MAXNORM);
#pragma unroll
    for (int j = 0; j < J; j++) hb[lane * J + j] = v[j] * f;
    if (lane == 0) *hbn2 = vn * vn;
}

// ---------------- kernel 1: gather + logmap0 + expmap0 + proj ----------------
// tasks t in [0, 24576): bid = t/6, k = t%6 (k==5 -> agent row). One warp/task.
__global__ void __launch_bounds__(256) k_gather(const float* __restrict__ in_nei,
                                                const float* __restrict__ in_feats) {
    const int tid = threadIdx.x, wid = tid >> 5, lane = tid & 31;
    const int t = blockIdx.x * 8 + wid;
    const int bid = t / 6;
    const int k = t - bid * 6;
    const float* fbase = in_feats + (bid >> 10) * (1024 * 32);

    float x = 0.f;
    if (k == 5) {
        float f = in_feats[bid * 32 + lane];
        float n, inv;
        norm_inv(wredsum(f * f), n, inv);
        x = __fdividef(artanh_fast(n), n) * f;
    } else {
        const float4* p4 = (const float4*)(in_nei + ((size_t)bid * 5 + k) * 1024);
        auto addc = [&](float w, int n) {
            if (w != 0.f) {   // warp-uniform (w broadcast)
                float f = fbase[n * 32 + lane];
                float nn, inv;
                norm_inv(wredsum(f * f), nn, inv);
                x = fmaf(w * __fdividef(artanh_fast(nn), nn), f, x);
            }
        };
#pragma unroll 1
        for (int pr = 0; pr < 4; pr++) {
            float4 a = p4[pr * 64 + lane];
            float4 b = p4[pr * 64 + 32 + lane];
            bool nz = (a.x != 0.f) || (a.y != 0.f) || (a.z != 0.f) || (a.w != 0.f) ||
                      (b.x != 0.f) || (b.y != 0.f) || (b.z != 0.f) || (b.w != 0.f);
            unsigned mk = __ballot_sync(FULLM, nz);
            if (mk) {
                while (mk) {
                    int src = __ffs(mk) - 1;
                    mk &= mk - 1u;
                    float ax = __shfl_sync(FULLM, a.x, src), ay = __shfl_sync(FULLM, a.y, src);
                    float az = __shfl_sync(FULLM, a.z, src), aw = __shfl_sync(FULLM, a.w, src);
                    float bx = __shfl_sync(FULLM, b.x, src), by = __shfl_sync(FULLM, b.y, src);
                    float bz = __shfl_sync(FULLM, b.z, src), bw = __shfl_sync(FULLM, b.w, src);
                    int na = pr * 256 + src * 4;
                    int nb = pr * 256 + 128 + src * 4;
                    addc(ax, na + 0); addc(ay, na + 1); addc(az, na + 2); addc(aw, na + 3);
                    addc(bx, nb + 0); addc(by, nb + 1); addc(bz, nb + 2); addc(bw, nb + 3);
                }
                break;   // one-hot row: first nonzero pair is the only one
            }
        }
    }
    float n, inv;
    norm_inv(wredsum(x * x), n, inv);
    float tt = tanh_fast(n);
    float f = (tt > MAXNORM) ? __fdividef(MAXNORM, tt) : 1.f;
    float pnr = fminf(tt, MAXNORM);
    g_p[(size_t)t * 32 + lane] = tt * inv * f * x;
    if (lane == 0)
        g_lam[t] = (pnr > 1e-6f) ? __fdividef(artanh_fast(pnr), pnr) : 1.f;
}

// ---------------- kernel 2: per-bid pipeline ----------------
// 8 warps/block, one bid per warp, grid = 512.
// Output ownership: thread(lane) owns m = j*32+lane for j = 0..4.
// smem (floats):
//   w1p [5120] : W1 d-pair packed: float2 wp[t*160 + m] = (W1[m][2t], W1[m][2t+1])
//                -> scalar index (d>>1)*320 + m*2 + (d&1)
//   w2t [1056], hb1[160], hb2[32], hbn[2], slab[8*992]
__global__ void __launch_bounds__(256, 3) k_bidpipe(const float* __restrict__ W1,
                                                    const float* __restrict__ b1,
                                                    const float* __restrict__ W2,
                                                    const float* __restrict__ b2,
                                                    float* __restrict__ outp,
                                                    float* __restrict__ attr) {
    extern __shared__ float sm[];
    float* w1p = sm;                    // 5120
    float* w2t = w1p + 5120;            // 1056
    float* hb1 = w2t + 1056;            // 160
    float* hb2 = hb1 + 160;             // 32
    float* hbn = hb2 + 32;              // 2
    float* slab = hbn + 2;              // 8*992

    const int tid = threadIdx.x, wid = tid >> 5, lane = tid & 31;

    if (wid == 0) {
        make_hyp_bias<5>(b1, hb1, &hbn[0]);
    } else if (wid == 1) {
        make_hyp_bias<1>(b2, hb2, &hbn[1]);
    } else {
        for (int i = tid - 64; i < 6144; i += 192) {
            if (i < 5120) {
                int m = i >> 5, d = i & 31;
                w1p[(d >> 1) * 320 + m * 2 + (d & 1)] = W1[i];
            } else {
                int j = i - 5120;
                int m = j >> 5, d = j & 31;
                w2t[d * 33 + m] = W2[j];
            }
        }
    }
    __syncthreads();

    const float hbn2 = hbn[0];
    float* myslab = slab + wid * 992;
    float hbl[5];
#pragma unroll
    for (int j = 0; j < 5; j++) hbl[j] = hb1[j * 32 + lane];   // hb[m], m = j*32+lane

    const int bid = blockIdx.x * 8 + wid;

    // ---- stage 6 ball points into the warp slab (scalar; read back as pairs) ----
#pragma unroll
    for (int r = 0; r < 6; r++)
        myslab[r * 32 + lane] = g_p[(size_t)(bid * 6 + r) * 32 + lane];
    __syncwarp();

    // ---- packed matvec: mx[r][j] = sum_d W1[m][d] * p[r][d], m = j*32+lane ----
    float mx[6][5];
    {
        const ull* wp64 = (const ull*)w1p;      // [t*160 + m]
        const ull* pp64 = (const ull*)myslab;   // [r*16 + t] broadcast pairs
#pragma unroll
        for (int half = 0; half < 2; half++) {
            ull acc[3][5];
#pragma unroll
            for (int r3 = 0; r3 < 3; r3++)
#pragma unroll
                for (int j = 0; j < 5; j++) acc[r3][j] = 0ull;
#pragma unroll
            for (int t = 0; t < 16; t++) {
                ull w[5];
#pragma unroll
                for (int j = 0; j < 5; j++) w[j] = wp64[t * 160 + j * 32 + lane];
                ull pv[3];
#pragma unroll
                for (int r3 = 0; r3 < 3; r3++) pv[r3] = pp64[(half * 3 + r3) * 16 + t];
#pragma unroll
                for (int r3 = 0; r3 < 3; r3++)
#pragma unroll
                    for (int j = 0; j < 5; j++)
                        acc[r3][j] = fma2(w[j], pv[r3], acc[r3][j]);
            }
#pragma unroll
            for (int r3 = 0; r3 < 3; r3++)
#pragma unroll
                for (int j = 0; j < 5; j++) {
                    float lo, hi;
                    unpack2(acc[r3][j], lo, hi);
                    mx[half * 3 + r3][j] = lo + hi;
                }
        }
    }

    // ---- per-lane partials for all 6 rows ----
    float s2[6], q[6];
#pragma unroll
    for (int r = 0; r < 6; r++) {
        float a = 0.f, b = 0.f;
#pragma unroll
        for (int j = 0; j < 5; j++) {
            a = fmaf(mx[r][j], mx[r][j], a);
            b = fmaf(mx[r][j], hbl[j], b);
        }
        s2[r] = a; q[r] = b;
    }
    // ---- ONE batched butterfly for all 12 sums ----
#pragma unroll
    for (int o = 16; o; o >>= 1) {
#pragma unroll
        for (int r = 0; r < 6; r++) {
            s2[r] += __shfl_xor_sync(FULLM, s2[r], o);
            q[r]  += __shfl_xor_sync(FULLM, q[r], o);
        }
    }
    // ---- lane-parallel scalar chain: lane r handles row r (r < 6) ----
    float s2l = s2[0], ql = q[0];
#pragma unroll
    for (int r = 1; r < 6; r++)
        if (lane == r) { s2l = s2[r]; ql = q[r]; }
    float laml = g_lam[bid * 6 + ((lane < 6) ? lane : 0)];

    float alpha, beta;
    {
        float zf = (s2l > 0.f) ? 1.f : 0.f;
        float mxn, inv2;
        norm_inv(s2l, mxn, inv2);
        float t2 = tanh_fast(mxn * laml);
        float rn = zf * t2;
        float fpr = (rn > MAXNORM) ? __fdividef(MAXNORM, rn) : 1.f;
        float sc = zf * t2 * inv2 * fpr;       // res = sc * mx
        float xy = sc * ql;                    // <res, hb>
        float rp = fminf(rn, MAXNORM);
        float x2 = rp * rp;                    // |res|^2 analytic
        float num_a = 1.f + 2.f * xy + hbn2;
        float num_b = 1.f - x2;
        float rden = __fdividef(1.f, fmaxf(1.f + 2.f * xy + x2 * hbn2, MINN));
        float s3 = rden * rden *
                   (num_a * num_a * x2 + 2.f * num_a * num_b * xy + num_b * num_b * hbn2);
        float hn = sqrtf(s3);
        float th = (hn > 1e-6f)
                       ? __fdividef(artanh_fast(fminf(hn, MAXNORM)), hn)
                       : 1.f;                  // proj + logmap0 combined
        alpha = th * num_a * sc * rden;
        beta  = th * num_b * rden;
    }
    float A[6], B[6];
#pragma unroll
    for (int r = 0; r < 6; r++) {
        A[r] = __shfl_sync(FULLM, alpha, r);
        B[r] = __shfl_sync(FULLM, beta, r);
    }
    // ---- xt = relu(.), batched s4 reduction ----
    float s4[6];
#pragma unroll
    for (int r = 0; r < 6; r++) {
        float a = 0.f;
#pragma unroll
        for (int j = 0; j < 5; j++) {
            float xt = fmaxf(fmaf(A[r], mx[r][j], B[r] * hbl[j]), 0.f);
            mx[r][j] = xt;
            a = fmaf(xt, xt, a);
        }
        s4[r] = a;
    }
#pragma unroll
    for (int o = 16; o; o >>= 1)
#pragma unroll
        for (int r = 0; r < 6; r++) s4[r] += __shfl_xor_sync(FULLM, s4[r], o);
    // ---- store heads into slab: element m = j*32+lane -> (h = m%5, d = m/5) ----
    int hidx[5], didx[5];
#pragma unroll
    for (int j = 0; j < 5; j++) {
        int mm = j * 32 + lane;
        didx[j] = mm / 5;
        hidx[j] = mm - didx[j] * 5;
    }
#pragma unroll
    for (int r = 0; r < 6; r++) {
        float oc = fminf(1.f, ATANH_MAX * __frsqrt_rn(fmaxf(s4[r], 1e-30f)));
#pragma unroll
        for (int j = 0; j < 5; j++)
            myslab[r * 165 + hidx[j] * 33 + didx[j]] = oc * mx[r][j];
    }
    __syncwarp();

    // ---- attention: lane -> (hh = lane/5, kk = lane%5), shfl-based softmax ----
    const int hh = lane / 5, kk = lane - hh * 5;
    float a_un = 0.f;
    if (lane < 25) {
        const float* ag = myslab + 5 * 165 + hh * 33;
        const float* ng = myslab + kk * 165 + hh * 33;
        float s = 0.f;
#pragma unroll
        for (int d = 0; d < 32; d++) s = fmaf(ag[d], ng[d], s);
        a_un = s;
    }
    float lg[5];
#pragma unroll
    for (int k2 = 0; k2 < 5; k2++)
        lg[k2] = __shfl_sync(FULLM, a_un, ((hh < 5) ? hh : 0) * 5 + k2);
    float aval = 0.f;
    {
        float m = lg[0];
#pragma unroll
        for (int k2 = 1; k2 < 5; k2++) m = fmaxf(m, lg[k2]);
        float se = 0.f;
#pragma unroll
        for (int k2 = 0; k2 < 5; k2++) se += __expf(lg[k2] - m);
        aval = __expf(a_un - m) * __fdividef(1.f, se);
        if (lane < 25) attr[(size_t)bid * 25 + lane] = aval;
    }

    // out[d=lane] = 0.2 * sum_{h,k} att[h][k] * neigh[k][h][d]
    float o = 0.f;
#pragma unroll
    for (int h2 = 0; h2 < 5; h2++)
#pragma unroll
        for (int k2 = 0; k2 < 5; k2++) {
            float av = __shfl_sync(FULLM, aval, h2 * 5 + k2);
            o = fmaf(av, myslab[k2 * 165 + h2 * 33 + lane], o);
        }
    o *= 0.2f;

    // ---- final W2 layer (ends with expmap0+proj) ----
    {
        const float hb2l = hb2[lane];
        const float hbn2b = hbn[1];
        float n, inv;
        norm_inv(wredsum(o * o), n, inv);
        float t = tanh_fast(n);
        float f = (t > MAXNORM) ? __fdividef(MAXNORM, t) : 1.f;
        float pp = t * inv * o * f;
        float ppn = fminf(t, MAXNORM);
        float lamb = (ppn > 1e-6f) ? __fdividef(artanh_fast(ppn), ppn) : 1.f;
        float mxv = 0.f;
#pragma unroll
        for (int d = 0; d < 32; d++) {
            float pd = __shfl_sync(FULLM, pp, d);
            mxv = fmaf(w2t[d * 33 + lane], pd, mxv);
        }
        float s2w = mxv * mxv, qw = mxv * hb2l;
        wredsum2(s2w, qw);
        float zf = (s2w > 0.f) ? 1.f : 0.f;
        float mxn, inv2;
        norm_inv(s2w, mxn, inv2);
        float t2 = tanh_fast(mxn * lamb);
        float rn = zf * t2;
        float fpr = (rn > MAXNORM) ? __fdividef(MAXNORM, rn) : 1.f;
        float sc = zf * t2 * inv2 * fpr;
        float xy = sc * qw;
        float rp = fminf(rn, MAXNORM);
        float x2 = rp * rp;
        float num_a = 1.f + 2.f * xy + hbn2b;
        float num_b = 1.f - x2;
        float rden = __fdividef(1.f, fmaxf(1.f + 2.f * xy + x2 * hbn2b, MINN));
        float s3 = rden * rden *
                   (num_a * num_a * x2 + 2.f * num_a * num_b * xy + num_b * num_b * hbn2b);
        float hn = sqrtf(s3);
        float th = (hn > 1e-6f)
                       ? __fdividef(artanh_fast(fminf(hn, MAXNORM)), hn)
                       : 1.f;
        float h = (num_a * sc * mxv + num_b * hb2l) * rden;
        float xt = fmaxf(th * h, 0.f);
        float tn, inv4;
        norm_inv(wredsum(xt * xt), tn, inv4);
        float t4 = tanh_fast(tn);
        float fo = (t4 > MAXNORM) ? __fdividef(MAXNORM, t4) : 1.f;
        outp[(size_t)bid * 32 + lane] = t4 * inv4 * fo * xt;
    }
}

extern "C" void kernel_launch(void* const* d_in, const int* in_sizes, int n_in,
                              void* d_out, int out_size) {
    const float* in_feats = (const float*)d_in[0];
    const float* in_nei   = (const float*)d_in[1];
    const float* W1       = (const float*)d_in[2];
    const float* b1       = (const float*)d_in[3];
    const float* W2       = (const float*)d_in[4];
    const float* b2       = (const float*)d_in[5];
    float* outp = (float*)d_out;
    float* attr = outp + 4 * 1024 * 32;   // out first, att_record second

    const int smem_bytes = (5120 + 1056 + 160 + 32 + 2 + 8 * 992) * 4;
    cudaFuncSetAttribute(k_bidpipe, cudaFuncAttributeMaxDynamicSharedMemorySize, smem_bytes);

    k_gather<<<3072, 256>>>(in_nei, in_feats);
    k_bidpipe<<<512, 256, smem_bytes>>>(W1, b1, W2, b2, outp, attr);
}

// round 15
// speedup vs baseline: 1.3129x; 1.3129x over previous
#include <cuda_runtime.h>
#include <math.h>

#define FULLM 0xffffffffu
#define MINN 1e-15f
#define MAXNORM 0.996f        // (1 - 0.004) / sqrt(c), c = 1
#define ATANH_MAX 3.1063030f  // artanh(0.996)

// ---------------- device scratch ----------------
__device__ float g_p[24576 * 32];   // ball-mapped rows (3.1MB, L2-resident)
__device__ float g_lam[24576];      // artanh(|p|)/|p| per row

// ---------------- helpers ----------------
__device__ __forceinline__ float wredsum(float v) {
#pragma unroll
    for (int o = 16; o; o >>= 1) v += __shfl_xor_sync(FULLM, v, o);
    return v;
}
__device__ __forceinline__ void wredsum2(float& a, float& b) {
#pragma unroll
    for (int o = 16; o; o >>= 1) {
        a += __shfl_xor_sync(FULLM, a, o);
        b += __shfl_xor_sync(FULLM, b, o);
    }
}
__device__ __forceinline__ float tanh_fast(float x) {   // x >= 0, clip 15
    x = fminf(x, 15.f);
    float e = __expf(-2.f * x);
    return __fdividef(1.f - e, 1.f + e);
}
__device__ __forceinline__ float artanh_fast(float x) {
    x = fminf(fmaxf(x, -1.f + 1e-7f), 1.f - 1e-7f);
    return 0.5f * __logf(__fdividef(1.f + x, 1.f - x));
}
__device__ __forceinline__ void norm_inv(float s, float& n, float& inv) {
    s = fmaxf(s, 1e-30f);
    inv = __frsqrt_rn(s);
    n = s * inv;
}

// hyp bias proj(expmap0(b)); warp-collective, writes smem
template <int J>
__device__ __forceinline__ void make_hyp_bias(const float* b, float* hb, float* hbn2) {
    const int lane = threadIdx.x & 31;
    float v[J];
    float s = 0.f;
#pragma unroll
    for (int j = 0; j < J; j++) { v[j] = b[lane * J + j]; s += v[j] * v[j]; }
    float n, inv;
    norm_inv(wredsum(s), n, inv);
    float t = tanh_fast(n);
#pragma unroll
    for (int j = 0; j < J; j++) v[j] *= t * inv;
    float f = (t > MAXNORM) ? __fdividef(MAXNORM, t) : 1.f;
    float vn = fminf(t, MAXNORM);
#pragma unroll
    for (int j = 0; j < J; j++) hb[lane * J + j] = v[j] * f;
    if (lane == 0) *hbn2 = vn * vn;
}

// ---------------- kernel 1: gather + logmap0 + expmap0 + proj ----------------
// tasks t in [0, 24576): bid = t/6, k = t%6 (k==5 -> agent row). One warp/task.
__global__ void __launch_bounds__(256) k_gather(const float* __restrict__ in_nei,
                                                const float* __restrict__ in_feats) {
    const int tid = threadIdx.x, wid = tid >> 5, lane = tid & 31;
    const int t = blockIdx.x * 8 + wid;
    const int bid = t / 6;
    const int k = t - bid * 6;
    const float* fbase = in_feats + (bid >> 10) * (1024 * 32);

    float x = 0.f;
    if (k == 5) {
        float f = in_feats[bid * 32 + lane];
        float n, inv;
        norm_inv(wredsum(f * f), n, inv);
        x = __fdividef(artanh_fast(n), n) * f;
    } else {
        const float4* p4 = (const float4*)(in_nei + ((size_t)bid * 5 + k) * 1024);
        auto addc = [&](float w, int n) {
            if (w != 0.f) {   // warp-uniform (w broadcast)
                float f = fbase[n * 32 + lane];
                float nn, inv;
                norm_inv(wredsum(f * f), nn, inv);
                x = fmaf(w * __fdividef(artanh_fast(nn), nn), f, x);
            }
        };
#pragma unroll 1
        for (int pr = 0; pr < 4; pr++) {
            float4 a = p4[pr * 64 + lane];
            float4 b = p4[pr * 64 + 32 + lane];
            bool nz = (a.x != 0.f) || (a.y != 0.f) || (a.z != 0.f) || (a.w != 0.f) ||
                      (b.x != 0.f) || (b.y != 0.f) || (b.z != 0.f) || (b.w != 0.f);
            unsigned mk = __ballot_sync(FULLM, nz);
            if (mk) {
                while (mk) {
                    int src = __ffs(mk) - 1;
                    mk &= mk - 1u;
                    float ax = __shfl_sync(FULLM, a.x, src), ay = __shfl_sync(FULLM, a.y, src);
                    float az = __shfl_sync(FULLM, a.z, src), aw = __shfl_sync(FULLM, a.w, src);
                    float bx = __shfl_sync(FULLM, b.x, src), by = __shfl_sync(FULLM, b.y, src);
                    float bz = __shfl_sync(FULLM, b.z, src), bw = __shfl_sync(FULLM, b.w, src);
                    int na = pr * 256 + src * 4;
                    int nb = pr * 256 + 128 + src * 4;
                    addc(ax, na + 0); addc(ay, na + 1); addc(az, na + 2); addc(aw, na + 3);
                    addc(bx, nb + 0); addc(by, nb + 1); addc(bz, nb + 2); addc(bw, nb + 3);
                }
                break;   // one-hot row: first nonzero pair is the only one
            }
        }
    }
    float n, inv;
    norm_inv(wredsum(x * x), n, inv);
    float tt = tanh_fast(n);
    float f = (tt > MAXNORM) ? __fdividef(MAXNORM, tt) : 1.f;
    float pnr = fminf(tt, MAXNORM);
    g_p[(size_t)t * 32 + lane] = tt * inv * f * x;
    if (lane == 0)
        g_lam[t] = (pnr > 1e-6f) ? __fdividef(artanh_fast(pnr), pnr) : 1.f;
}

// ---------------- kernel 2: per-bid pipeline, TWO warps per bid ----------------
// 8 warps/block = 4 bids/block, grid = 1024.
// Warp w: bidLocal = w/2, half = w%2, rows = half*3 + {0,1,2}.
// smem (floats): w1t[5152] ([d*161 + m], m = lane*5+j), w2t[1056],
//                hb1[160], hb2[32], hbn[2], slab[4*992] ([bidLocal][r*165 + j*33 + d])
__global__ void __launch_bounds__(256, 4) k_bidpipe(const float* __restrict__ W1,
                                                    const float* __restrict__ b1,
                                                    const float* __restrict__ W2,
                                                    const float* __restrict__ b2,
                                                    float* __restrict__ outp,
                                                    float* __restrict__ attr) {
    extern __shared__ float sm[];
    float* w1t = sm;                    // 5152
    float* w2t = w1t + 5152;            // 1056
    float* hb1 = w2t + 1056;            // 160
    float* hb2 = hb1 + 160;             // 32
    float* hbn = hb2 + 32;              // 2
    float* slab = hbn + 2;              // 4*992

    const int tid = threadIdx.x, wid = tid >> 5, lane = tid & 31;

    if (wid == 0) {
        make_hyp_bias<5>(b1, hb1, &hbn[0]);
    } else if (wid == 1) {
        make_hyp_bias<1>(b2, hb2, &hbn[1]);
    } else {
        for (int i = tid - 64; i < 6208; i += 192) {
            if (i < 5152) {
                int m = i >> 5, d = i & 31;
                w1t[d * 161 + m] = W1[i];
            } else {
                int j = i - 5152;
                int m = j >> 5, d = j & 31;
                w2t[d * 33 + m] = W2[j];
            }
        }
    }
    __syncthreads();

    const float hbn2 = hbn[0];
    const int bidLocal = wid >> 1, half = wid & 1;
    const int bid = blockIdx.x * 4 + bidLocal;
    float* myslab = slab + bidLocal * 992;
    float hbl[5];
#pragma unroll
    for (int j = 0; j < 5; j++) hbl[j] = hb1[lane * 5 + j];

    // ---- this warp's 3 rows ----
    const int r0 = half * 3;
    float p[3];
#pragma unroll
    for (int r = 0; r < 3; r++)
        p[r] = g_p[(size_t)(bid * 6 + r0 + r) * 32 + lane];

    // ---- matvec: mx[r][j] = sum_d W1[lane*5+j][d] * p[r][d] ----
    float mx[3][5];
#pragma unroll
    for (int r = 0; r < 3; r++)
#pragma unroll
        for (int j = 0; j < 5; j++) mx[r][j] = 0.f;
#pragma unroll
    for (int d = 0; d < 32; d++) {
        float w0 = w1t[d * 161 + lane * 5 + 0];
        float w1 = w1t[d * 161 + lane * 5 + 1];
        float w2 = w1t[d * 161 + lane * 5 + 2];
        float w3 = w1t[d * 161 + lane * 5 + 3];
        float w4 = w1t[d * 161 + lane * 5 + 4];
#pragma unroll
        for (int r = 0; r < 3; r++) {
            float pd = __shfl_sync(FULLM, p[r], d);
            mx[r][0] = fmaf(w0, pd, mx[r][0]);
            mx[r][1] = fmaf(w1, pd, mx[r][1]);
            mx[r][2] = fmaf(w2, pd, mx[r][2]);
            mx[r][3] = fmaf(w3, pd, mx[r][3]);
            mx[r][4] = fmaf(w4, pd, mx[r][4]);
        }
    }

    // ---- per-lane partials for the 3 rows ----
    float s2[3], q[3];
#pragma unroll
    for (int r = 0; r < 3; r++) {
        float a = 0.f, b = 0.f;
#pragma unroll
        for (int j = 0; j < 5; j++) {
            a = fmaf(mx[r][j], mx[r][j], a);
            b = fmaf(mx[r][j], hbl[j], b);
        }
        s2[r] = a; q[r] = b;
    }
    // ---- ONE batched butterfly for all 6 sums ----
#pragma unroll
    for (int o = 16; o; o >>= 1) {
#pragma unroll
        for (int r = 0; r < 3; r++) {
            s2[r] += __shfl_xor_sync(FULLM, s2[r], o);
            q[r]  += __shfl_xor_sync(FULLM, q[r], o);
        }
    }
    // ---- lane-parallel scalar chain: lane r handles row r (r < 3) ----
    float s2l = s2[0], ql = q[0];
#pragma unroll
    for (int r = 1; r < 3; r++)
        if (lane == r) { s2l = s2[r]; ql = q[r]; }
    float laml = g_lam[bid * 6 + r0 + ((lane < 3) ? lane : 0)];

    float alpha, beta;
    {
        float zf = (s2l > 0.f) ? 1.f : 0.f;
        float mxn, inv2;
        norm_inv(s2l, mxn, inv2);
        float t2 = tanh_fast(mxn * laml);
        float rn = zf * t2;
        float fpr = (rn > MAXNORM) ? __fdividef(MAXNORM, rn) : 1.f;
        float sc = zf * t2 * inv2 * fpr;       // res = sc * mx
        float xy = sc * ql;                    // <res, hb>
        float rp = fminf(rn, MAXNORM);
        float x2 = rp * rp;                    // |res|^2 analytic
        float num_a = 1.f + 2.f * xy + hbn2;
        float num_b = 1.f - x2;
        float rden = __fdividef(1.f, fmaxf(1.f + 2.f * xy + x2 * hbn2, MINN));
        float s3 = rden * rden *
                   (num_a * num_a * x2 + 2.f * num_a * num_b * xy + num_b * num_b * hbn2);
        float hn = sqrtf(s3);
        float th = (hn > 1e-6f)
                       ? __fdividef(artanh_fast(fminf(hn, MAXNORM)), hn)
                       : 1.f;                  // proj + logmap0 combined
        alpha = th * num_a * sc * rden;
        beta  = th * num_b * rden;
    }
    float A[3], B[3];
#pragma unroll
    for (int r = 0; r < 3; r++) {
        A[r] = __shfl_sync(FULLM, alpha, r);
        B[r] = __shfl_sync(FULLM, beta, r);
    }
    // ---- xt = relu(.), batched s4 reduction ----
    float s4[3];
#pragma unroll
    for (int r = 0; r < 3; r++) {
        float a = 0.f;
#pragma unroll
        for (int j = 0; j < 5; j++) {
            float xt = fmaxf(fmaf(A[r], mx[r][j], B[r] * hbl[j]), 0.f);
            mx[r][j] = xt;
            a = fmaf(xt, xt, a);
        }
        s4[r] = a;
    }
#pragma unroll
    for (int o = 16; o; o >>= 1)
#pragma unroll
        for (int r = 0; r < 3; r++) s4[r] += __shfl_xor_sync(FULLM, s4[r], o);
    // ---- store heads into the bid slab ----
#pragma unroll
    for (int r = 0; r < 3; r++) {
        float oc = fminf(1.f, ATANH_MAX * __frsqrt_rn(fmaxf(s4[r], 1e-30f)));
#pragma unroll
        for (int j = 0; j < 5; j++)
            myslab[(r0 + r) * 165 + j * 33 + lane] = oc * mx[r][j];
    }
    __syncthreads();   // both halves' rows visible

    // ---- attention + output + W2: only the half==0 warp of each pair ----
    if (half) return;

    const int hh = lane / 5, kk = lane - hh * 5;
    float a_un = 0.f;
    if (lane < 25) {
        const float* ag = myslab + 5 * 165 + hh * 33;
        const float* ng = myslab + kk * 165 + hh * 33;
        float s = 0.f;
#pragma unroll
        for (int d = 0; d < 32; d++) s = fmaf(ag[d], ng[d], s);
        a_un = s;
    }
    float lg[5];
#pragma unroll
    for (int k2 = 0; k2 < 5; k2++)
        lg[k2] = __shfl_sync(FULLM, a_un, ((hh < 5) ? hh : 0) * 5 + k2);
    float aval = 0.f;
    {
        float m = lg[0];
#pragma unroll
        for (int k2 = 1; k2 < 5; k2++) m = fmaxf(m, lg[k2]);
        float se = 0.f;
#pragma unroll
        for (int k2 = 0; k2 < 5; k2++) se += __expf(lg[k2] - m);
        aval = __expf(a_un - m) * __fdividef(1.f, se);
        if (lane < 25) attr[(size_t)bid * 25 + lane] = aval;
    }

    // out[d=lane] = 0.2 * sum_{h,k} att[h][k] * neigh[k][h][d]
    float o = 0.f;
#pragma unroll
    for (int h2 = 0; h2 < 5; h2++)
#pragma unroll
        for (int k2 = 0; k2 < 5; k2++) {
            float av = __shfl_sync(FULLM, aval, h2 * 5 + k2);
            o = fmaf(av, myslab[k2 * 165 + h2 * 33 + lane], o);
        }
    o *= 0.2f;

    // ---- final W2 layer (ends with expmap0+proj) ----
    {
        const float hb2l = hb2[lane];
        const float hbn2b = hbn[1];
        float n, inv;
        norm_inv(wredsum(o * o), n, inv);
        float t = tanh_fast(n);
        float f = (t > MAXNORM) ? __fdividef(MAXNORM, t) : 1.f;
        float pp = t * inv * o * f;
        float ppn = fminf(t, MAXNORM);
        float lamb = (ppn > 1e-6f) ? __fdividef(artanh_fast(ppn), ppn) : 1.f;
        float mxv = 0.f;
#pragma unroll
        for (int d = 0; d < 32; d++) {
            float pd = __shfl_sync(FULLM, pp, d);
            mxv = fmaf(w2t[d * 33 + lane], pd, mxv);
        }
        float s2w = mxv * mxv, qw = mxv * hb2l;
        wredsum2(s2w, qw);
        float zf = (s2w > 0.f) ? 1.f : 0.f;
        float mxn, inv2;
        norm_inv(s2w, mxn, inv2);
        float t2 = tanh_fast(mxn * lamb);
        float rn = zf * t2;
        float fpr = (rn > MAXNORM) ? __fdividef(MAXNORM, rn) : 1.f;
        float sc = zf * t2 * inv2 * fpr;
        float xy = sc * qw;
        float rp = fminf(rn, MAXNORM);
        float x2 = rp * rp;
        float num_a = 1.f + 2.f * xy + hbn2b;
        float num_b = 1.f - x2;
        float rden = __fdividef(1.f, fmaxf(1.f + 2.f * xy + x2 * hbn2b, MINN));
        float s3 = rden * rden *
                   (num_a * num_a * x2 + 2.f * num_a * num_b * xy + num_b * num_b * hbn2b);
        float hn = sqrtf(s3);
        float th = (hn > 1e-6f)
                       ? __fdividef(artanh_fast(fminf(hn, MAXNORM)), hn)
                       : 1.f;
        float h = (num_a * sc * mxv + num_b * hb2l) * rden;
        float xt = fmaxf(th * h, 0.f);
        float tn, inv4;
        norm_inv(wredsum(xt * xt), tn, inv4);
        float t4 = tanh_fast(tn);
        float fo = (t4 > MAXNORM) ? __fdividef(MAXNORM, t4) : 1.f;
        outp[(size_t)bid * 32 + lane] = t4 * inv4 * fo * xt;
    }
}

extern "C" void kernel_launch(void* const* d_in, const int* in_sizes, int n_in,
                              void* d_out, int out_size) {
    const float* in_feats = (const float*)d_in[0];
    const float* in_nei   = (const float*)d_in[1];
    const float* W1       = (const float*)d_in[2];
    const float* b1       = (const float*)d_in[3];
    const float* W2       = (const float*)d_in[4];
    const float* b2       = (const float*)d_in[5];
    float* outp = (float*)d_out;
    float* attr = outp + 4 * 1024 * 32;   // out first, att_record second

    const int smem_bytes = (5152 + 1056 + 160 + 32 + 2 + 4 * 992) * 4;
    cudaFuncSetAttribute(k_bidpipe, cudaFuncAttributeMaxDynamicSharedMemorySize, smem_bytes);

    k_gather<<<3072, 256>>>(in_nei, in_feats);
    k_bidpipe<<<1024, 256, smem_bytes>>>(W1, b1, W2, b2, outp, attr);
}

// round 16
// speedup vs baseline: 1.4229x; 1.0838x over previous
#include <cuda_runtime.h>
#include <math.h>

#define FULLM 0xffffffffu
#define MINN 1e-15f
#define MAXNORM 0.996f        // (1 - 0.004) / sqrt(c), c = 1
#define ATANH_MAX 3.1063030f  // artanh(0.996)

// ---------------- device scratch ----------------
__device__ float g_p[24576 * 32];   // ball-mapped rows (3.1MB, L2-resident)
__device__ float g_lam[24576];      // artanh(|p|)/|p| per row

// ---------------- helpers ----------------
__device__ __forceinline__ float wredsum(float v) {
#pragma unroll
    for (int o = 16; o; o >>= 1) v += __shfl_xor_sync(FULLM, v, o);
    return v;
}
__device__ __forceinline__ void wredsum2(float& a, float& b) {
#pragma unroll
    for (int o = 16; o; o >>= 1) {
        a += __shfl_xor_sync(FULLM, a, o);
        b += __shfl_xor_sync(FULLM, b, o);
    }
}
__device__ __forceinline__ float tanh_fast(float x) {   // x >= 0, clip 15
    x = fminf(x, 15.f);
    float e = __expf(-2.f * x);
    return __fdividef(1.f - e, 1.f + e);
}
__device__ __forceinline__ float artanh_fast(float x) {
    x = fminf(fmaxf(x, -1.f + 1e-7f), 1.f - 1e-7f);
    return 0.5f * __logf(__fdividef(1.f + x, 1.f - x));
}
__device__ __forceinline__ void norm_inv(float s, float& n, float& inv) {
    s = fmaxf(s, 1e-30f);
    inv = __frsqrt_rn(s);
    n = s * inv;
}

// hyp bias proj(expmap0(b)); warp-collective, writes smem
template <int J>
__device__ __forceinline__ void make_hyp_bias(const float* b, float* hb, float* hbn2) {
    const int lane = threadIdx.x & 31;
    float v[J];
    float s = 0.f;
#pragma unroll
    for (int j = 0; j < J; j++) { v[j] = b[lane * J + j]; s += v[j] * v[j]; }
    float n, inv;
    norm_inv(wredsum(s), n, inv);
    float t = tanh_fast(n);
#pragma unroll
    for (int j = 0; j < J; j++) v[j] *= t * inv;
    float f = (t > MAXNORM) ? __fdividef(MAXNORM, t) : 1.f;
    float vn = fminf(t, MAXNORM);
#pragma unroll
    for (int j = 0; j < J; j++) hb[lane * J + j] = v[j] * f;
    if (lane == 0) *hbn2 = vn * vn;
}

// ---------------- kernel 1: gather + logmap0 + expmap0 + proj ----------------
// tasks t in [0, 24576): bid = t/6, k = t%6 (k==5 -> agent row). One warp/task.
__global__ void __launch_bounds__(256) k_gather(const float* __restrict__ in_nei,
                                                const float* __restrict__ in_feats) {
    const int tid = threadIdx.x, wid = tid >> 5, lane = tid & 31;
    const int t = blockIdx.x * 8 + wid;
    const int bid = t / 6;
    const int k = t - bid * 6;
    const float* fbase = in_feats + (bid >> 10) * (1024 * 32);

    float x = 0.f;
    if (k == 5) {
        float f = in_feats[bid * 32 + lane];
        float n, inv;
        norm_inv(wredsum(f * f), n, inv);
        x = __fdividef(artanh_fast(n), n) * f;
    } else {
        const float4* p4 = (const float4*)(in_nei + ((size_t)bid * 5 + k) * 1024);
        auto addc = [&](float w, int n) {
            if (w != 0.f) {   // warp-uniform (w broadcast)
                float f = fbase[n * 32 + lane];
                float nn, inv;
                norm_inv(wredsum(f * f), nn, inv);
                x = fmaf(w * __fdividef(artanh_fast(nn), nn), f, x);
            }
        };
#pragma unroll 1
        for (int pr = 0; pr < 4; pr++) {
            float4 a = p4[pr * 64 + lane];
            float4 b = p4[pr * 64 + 32 + lane];
            bool nz = (a.x != 0.f) || (a.y != 0.f) || (a.z != 0.f) || (a.w != 0.f) ||
                      (b.x != 0.f) || (b.y != 0.f) || (b.z != 0.f) || (b.w != 0.f);
            unsigned mk = __ballot_sync(FULLM, nz);
            if (mk) {
                while (mk) {
                    int src = __ffs(mk) - 1;
                    mk &= mk - 1u;
                    float ax = __shfl_sync(FULLM, a.x, src), ay = __shfl_sync(FULLM, a.y, src);
                    float az = __shfl_sync(FULLM, a.z, src), aw = __shfl_sync(FULLM, a.w, src);
                    float bx = __shfl_sync(FULLM, b.x, src), by = __shfl_sync(FULLM, b.y, src);
                    float bz = __shfl_sync(FULLM, b.z, src), bw = __shfl_sync(FULLM, b.w, src);
                    int na = pr * 256 + src * 4;
                    int nb = pr * 256 + 128 + src * 4;
                    addc(ax, na + 0); addc(ay, na + 1); addc(az, na + 2); addc(aw, na + 3);
                    addc(bx, nb + 0); addc(by, nb + 1); addc(bz, nb + 2); addc(bw, nb + 3);
                }
                break;   // one-hot row: first nonzero pair is the only one
            }
        }
    }
    float n, inv;
    norm_inv(wredsum(x * x), n, inv);
    float tt = tanh_fast(n);
    float f = (tt > MAXNORM) ? __fdividef(MAXNORM, tt) : 1.f;
    float pnr = fminf(tt, MAXNORM);
    g_p[(size_t)t * 32 + lane] = tt * inv * f * x;
    if (lane == 0)
        g_lam[t] = (pnr > 1e-6f) ? __fdividef(artanh_fast(pnr), pnr) : 1.f;
}

// ---------------- kernel 2: per-bid pipeline ----------------
// 8 warps/block, TWO bids per warp, grid = 256 -> single wave, prologue amortized 2x.
__global__ void __launch_bounds__(256, 3) k_bidpipe(const float* __restrict__ W1,
                                                    const float* __restrict__ b1,
                                                    const float* __restrict__ W2,
                                                    const float* __restrict__ b2,
                                                    float* __restrict__ outp,
                                                    float* __restrict__ attr) {
    extern __shared__ float sm[];
    float* w1t = sm;                    // 5152  [d*161 + m], m = lane*5+j
    float* w2t = w1t + 5152;            // 1056  [d*33 + m]
    float* hb1 = w2t + 1056;            // 160
    float* hb2 = hb1 + 160;             // 32
    float* hbn = hb2 + 32;              // 2
    float* slab = hbn + 2;              // 8*1008  [wid][r*168 + j*33 + d]
    float* attws = slab + 8 * 1008;     // 8*32

    const int tid = threadIdx.x, wid = tid >> 5, lane = tid & 31;

    if (wid == 0) {
        make_hyp_bias<5>(b1, hb1, &hbn[0]);
    } else if (wid == 1) {
        make_hyp_bias<1>(b2, hb2, &hbn[1]);
    } else {
        for (int i = tid - 64; i < 6208; i += 192) {
            if (i < 5152) {
                int m = i >> 5, d = i & 31;
                w1t[d * 161 + m] = W1[i];
            } else {
                int j = i - 5152;
                int m = j >> 5, d = j & 31;
                w2t[d * 33 + m] = W2[j];
            }
        }
    }
    __syncthreads();

    const float hbn2 = hbn[0];
    float* myslab = slab + wid * 1008;
    float* attw = attws + wid * 32;
    float hbl[5];
#pragma unroll
    for (int j = 0; j < 5; j++) hbl[j] = hb1[lane * 5 + j];

#pragma unroll 1
    for (int rep = 0; rep < 2; rep++) {
        const int bid = (blockIdx.x * 8 + wid) * 2 + rep;

        // ---- load 6 ball points ----
        float p[6];
#pragma unroll
        for (int r = 0; r < 6; r++) p[r] = g_p[(size_t)(bid * 6 + r) * 32 + lane];

        // ---- batched matvec: mx[r][j] = sum_d W1[lane*5+j][d] * p[r][d] ----
        float mx[6][5];
#pragma unroll
        for (int r = 0; r < 6; r++)
#pragma unroll
            for (int j = 0; j < 5; j++) mx[r][j] = 0.f;
#pragma unroll
        for (int d = 0; d < 32; d++) {
            float w0 = w1t[d * 161 + lane * 5 + 0];
            float w1 = w1t[d * 161 + lane * 5 + 1];
            float w2 = w1t[d * 161 + lane * 5 + 2];
            float w3 = w1t[d * 161 + lane * 5 + 3];
            float w4 = w1t[d * 161 + lane * 5 + 4];
#pragma unroll
            for (int r = 0; r < 6; r++) {
                float pd = __shfl_sync(FULLM, p[r], d);
                mx[r][0] = fmaf(w0, pd, mx[r][0]);
                mx[r][1] = fmaf(w1, pd, mx[r][1]);
                mx[r][2] = fmaf(w2, pd, mx[r][2]);
                mx[r][3] = fmaf(w3, pd, mx[r][3]);
                mx[r][4] = fmaf(w4, pd, mx[r][4]);
            }
        }

        // ---- per-lane partials for all 6 rows ----
        float s2[6], q[6];
#pragma unroll
        for (int r = 0; r < 6; r++) {
            float a = 0.f, b = 0.f;
#pragma unroll
            for (int j = 0; j < 5; j++) {
                a = fmaf(mx[r][j], mx[r][j], a);
                b = fmaf(mx[r][j], hbl[j], b);
            }
            s2[r] = a; q[r] = b;
        }
        // ---- ONE batched butterfly for all 12 sums ----
#pragma unroll
        for (int o = 16; o; o >>= 1) {
#pragma unroll
            for (int r = 0; r < 6; r++) {
                s2[r] += __shfl_xor_sync(FULLM, s2[r], o);
                q[r]  += __shfl_xor_sync(FULLM, q[r], o);
            }
        }
        // ---- lane-parallel scalar chain: lane r handles row r (r < 6) ----
        float s2l = s2[0], ql = q[0];
#pragma unroll
        for (int r = 1; r < 6; r++)
            if (lane == r) { s2l = s2[r]; ql = q[r]; }
        float laml = g_lam[bid * 6 + ((lane < 6) ? lane : 0)];

        float alpha, beta;
        {
            float zf = (s2l > 0.f) ? 1.f : 0.f;
            float mxn, inv2;
            norm_inv(s2l, mxn, inv2);
            float t2 = tanh_fast(mxn * laml);
            float rn = zf * t2;
            float fpr = (rn > MAXNORM) ? __fdividef(MAXNORM, rn) : 1.f;
            float sc = zf * t2 * inv2 * fpr;       // res = sc * mx
            float xy = sc * ql;                    // <res, hb>
            float rp = fminf(rn, MAXNORM);
            float x2 = rp * rp;                    // |res|^2 analytic
            float num_a = 1.f + 2.f * xy + hbn2;
            float num_b = 1.f - x2;
            float rden = __fdividef(1.f, fmaxf(1.f + 2.f * xy + x2 * hbn2, MINN));
            float s3 = rden * rden *
                       (num_a * num_a * x2 + 2.f * num_a * num_b * xy + num_b * num_b * hbn2);
            float hn = sqrtf(s3);
            float th = (hn > 1e-6f)
                           ? __fdividef(artanh_fast(fminf(hn, MAXNORM)), hn)
                           : 1.f;                  // proj + logmap0 combined
            alpha = th * num_a * sc * rden;
            beta  = th * num_b * rden;
        }
        float A[6], B[6];
#pragma unroll
        for (int r = 0; r < 6; r++) {
            A[r] = __shfl_sync(FULLM, alpha, r);
            B[r] = __shfl_sync(FULLM, beta, r);
        }
        // ---- xt = relu(.), batched s4 reduction ----
        float s4[6];
#pragma unroll
        for (int r = 0; r < 6; r++) {
            float a = 0.f;
#pragma unroll
            for (int j = 0; j < 5; j++) {
                float xt = fmaxf(fmaf(A[r], mx[r][j], B[r] * hbl[j]), 0.f);
                mx[r][j] = xt;
                a = fmaf(xt, xt, a);
            }
            s4[r] = a;
        }
#pragma unroll
        for (int o = 16; o; o >>= 1)
#pragma unroll
            for (int r = 0; r < 6; r++) s4[r] += __shfl_xor_sync(FULLM, s4[r], o);
        // ---- store heads into slab ----
#pragma unroll
        for (int r = 0; r < 6; r++) {
            float oc = fminf(1.f, ATANH_MAX * __frsqrt_rn(fmaxf(s4[r], 1e-30f)));
#pragma unroll
            for (int j = 0; j < 5; j++) myslab[r * 168 + j * 33 + lane] = oc * mx[r][j];
        }
        __syncwarp();

        // ---- attention: lane -> (hh = lane/5, kk = lane%5) ----
        const int hh = lane / 5, kk = lane - hh * 5;
        float a_un = 0.f;
        if (lane < 25) {
            const float* ag = myslab + 5 * 168 + hh * 33;
            const float* ng = myslab + kk * 168 + hh * 33;
            float s = 0.f;
#pragma unroll
            for (int d = 0; d < 32; d++) s = fmaf(ag[d], ng[d], s);
            a_un = s;
        }
        attw[lane] = a_un;
        __syncwarp();
        float aval = 0.f;
        if (lane < 25) {
            float m = -3.4e38f;
#pragma unroll
            for (int k2 = 0; k2 < 5; k2++) m = fmaxf(m, attw[hh * 5 + k2]);
            float se = 0.f;
#pragma unroll
            for (int k2 = 0; k2 < 5; k2++) se += __expf(attw[hh * 5 + k2] - m);
            aval = __expf(a_un - m) * __fdividef(1.f, se);
            attr[(size_t)bid * 25 + lane] = aval;
        }
        attw[lane] = aval;
        __syncwarp();

        float o = 0.f;
#pragma unroll
        for (int h2 = 0; h2 < 5; h2++)
#pragma unroll
            for (int k2 = 0; k2 < 5; k2++)
                o = fmaf(attw[h2 * 5 + k2], myslab[k2 * 168 + h2 * 33 + lane], o);
        o *= 0.2f;

        // ---- final W2 layer (ends with expmap0+proj) ----
        {
            const float hb2l = hb2[lane];
            const float hbn2b = hbn[1];
            float n, inv;
            norm_inv(wredsum(o * o), n, inv);
            float t = tanh_fast(n);
            float f = (t > MAXNORM) ? __fdividef(MAXNORM, t) : 1.f;
            float pp = t * inv * o * f;
            float ppn = fminf(t, MAXNORM);
            float lamb = (ppn > 1e-6f) ? __fdividef(artanh_fast(ppn), ppn) : 1.f;
            float mxv = 0.f;
#pragma unroll
            for (int d = 0; d < 32; d++) {
                float pd = __shfl_sync(FULLM, pp, d);
                mxv = fmaf(w2t[d * 33 + lane], pd, mxv);
            }
            float s2w = mxv * mxv, qw = mxv * hb2l;
            wredsum2(s2w, qw);
            float zf = (s2w > 0.f) ? 1.f : 0.f;
            float mxn, inv2;
            norm_inv(s2w, mxn, inv2);
            float t2 = tanh_fast(mxn * lamb);
            float rn = zf * t2;
            float fpr = (rn > MAXNORM) ? __fdividef(MAXNORM, rn) : 1.f;
            float sc = zf * t2 * inv2 * fpr;
            float xy = sc * qw;
            float rp = fminf(rn, MAXNORM);
            float x2 = rp * rp;
            float num_a = 1.f + 2.f * xy + hbn2b;
            float num_b = 1.f - x2;
            float rden = __fdividef(1.f, fmaxf(1.f + 2.f * xy + x2 * hbn2b, MINN));
            float s3 = rden * rden *
                       (num_a * num_a * x2 + 2.f * num_a * num_b * xy + num_b * num_b * hbn2b);
            float hn = sqrtf(s3);
            float th = (hn > 1e-6f)
                           ? __fdividef(artanh_fast(fminf(hn, MAXNORM)), hn)
                           : 1.f;
            float h = (num_a * sc * mxv + num_b * hb2l) * rden;
            float xt = fmaxf(th * h, 0.f);
            float tn, inv4;
            norm_inv(wredsum(xt * xt), tn, inv4);
            float t4 = tanh_fast(tn);
            float fo = (t4 > MAXNORM) ? __fdividef(MAXNORM, t4) : 1.f;
            outp[(size_t)bid * 32 + lane] = t4 * inv4 * fo * xt;
        }
        __syncwarp();
    }
}

extern "C" void kernel_launch(void* const* d_in, const int* in_sizes, int n_in,
                              void* d_out, int out_size) {
    const float* in_feats = (const float*)d_in[0];
    const float* in_nei   = (const float*)d_in[1];
    const float* W1       = (const float*)d_in[2];
    const float* b1       = (const float*)d_in[3];
    const float* W2       = (const float*)d_in[4];
    const float* b2       = (const float*)d_in[5];
    float* outp = (float*)d_out;
    float* attr = outp + 4 * 1024 * 32;   // out first, att_record second

    const int smem_bytes = (5152 + 1056 + 160 + 32 + 2 + 8 * 1008 + 8 * 32) * 4;
    cudaFuncSetAttribute(k_bidpipe, cudaFuncAttributeMaxDynamicSharedMemorySize, smem_bytes);

    k_gather<<<3072, 256>>>(in_nei, in_feats);
    k_bidpipe<<<256, 256, smem_bytes>>>(W1, b1, W2, b2, outp, attr);
}